// round 4
// baseline (speedup 1.0000x reference)
#include <cuda_runtime.h>

// MLP_52759378264652: B=1048576 rows, stem Linear(2,4)+ReLU,
// 98x [Linear(4,4)+Sigmoid], head Linear(4,1).
// Strategy: weights in shared (pre-scaled by -log2e so sigmoid is
// rcp(1+ex2(y'))), R rows per thread, coalesced float2/float I/O.

#define N_MID 98
#define BATCH 1048576
#define RPT 8
#define TPB 256
#define TOTAL_THREADS (BATCH / RPT)       // 131072
#define NBLOCKS (TOTAL_THREADS / TPB)     // 512

__device__ __forceinline__ float ex2_approx(float x) {
    float r; asm("ex2.approx.f32 %0, %1;" : "=f"(r) : "f"(x)); return r;
}
__device__ __forceinline__ float rcp_approx(float x) {
    float r; asm("rcp.approx.f32 %0, %1;" : "=f"(r) : "f"(x)); return r;
}

__global__ __launch_bounds__(TPB) void mlp_kernel(
    const float* __restrict__ x,      // [B,2]
    const float* __restrict__ W_in,   // [4,2]
    const float* __restrict__ b_in,   // [4]
    const float* __restrict__ W_mid,  // [98,4,4]
    const float* __restrict__ b_mid,  // [98,4]
    const float* __restrict__ W_out,  // [1,4]
    const float* __restrict__ b_out,  // [1]
    float* __restrict__ out)          // [B,1]
{
    // Per-layer block of 20 floats: W[4][4] then b[4], both scaled by -log2e.
    // Stride 20 floats = 80 B (16B-aligned) so float4 loads work at +0/4/8/12/16.
    __shared__ float sW[N_MID * 20];
    __shared__ float sWin[8];
    __shared__ float sbin[4];
    __shared__ float sWout[4];
    __shared__ float sbout;

    const float NEG_LOG2E = -1.4426950408889634f;

    for (int idx = threadIdx.x; idx < N_MID * 16; idx += TPB) {
        int l = idx >> 4, r = idx & 15;
        sW[l * 20 + r] = W_mid[idx] * NEG_LOG2E;
    }
    for (int idx = threadIdx.x; idx < N_MID * 4; idx += TPB) {
        int l = idx >> 2, r = idx & 3;
        sW[l * 20 + 16 + r] = b_mid[idx] * NEG_LOG2E;
    }
    if (threadIdx.x < 8) sWin[threadIdx.x] = W_in[threadIdx.x];
    if (threadIdx.x < 4) {
        sbin[threadIdx.x]  = b_in[threadIdx.x];
        sWout[threadIdx.x] = W_out[threadIdx.x];
    }
    if (threadIdx.x == 0) sbout = b_out[0];
    __syncthreads();

    const int tid = blockIdx.x * TPB + threadIdx.x;

    float h[RPT][4];

    // ---- stem: Linear(2,4) + ReLU, coalesced float2 loads ----
    const float2* x2 = reinterpret_cast<const float2*>(x);
    #pragma unroll
    for (int k = 0; k < RPT; k++) {
        float2 xv = x2[tid + k * TOTAL_THREADS];
        #pragma unroll
        for (int j = 0; j < 4; j++) {
            float v = fmaf(xv.x, sWin[2 * j],
                      fmaf(xv.y, sWin[2 * j + 1], sbin[j]));
            h[k][j] = fmaxf(v, 0.0f);
        }
    }

    // ---- 98 x [Linear(4,4) + Sigmoid] ----
    #pragma unroll 1
    for (int l = 0; l < N_MID; l++) {
        const float4* wp = reinterpret_cast<const float4*>(sW + l * 20);
        float4 w0 = wp[0];   // row 0 of (-log2e * W)
        float4 w1 = wp[1];
        float4 w2 = wp[2];
        float4 w3 = wp[3];
        float4 bb = wp[4];   // -log2e * b

        #pragma unroll
        for (int k = 0; k < RPT; k++) {
            float h0 = h[k][0], h1 = h[k][1], h2 = h[k][2], h3 = h[k][3];
            // y' = -log2e * (h @ W^T + b)
            float y0 = fmaf(h0, w0.x, fmaf(h1, w0.y, fmaf(h2, w0.z, fmaf(h3, w0.w, bb.x))));
            float y1 = fmaf(h0, w1.x, fmaf(h1, w1.y, fmaf(h2, w1.z, fmaf(h3, w1.w, bb.y))));
            float y2 = fmaf(h0, w2.x, fmaf(h1, w2.y, fmaf(h2, w2.z, fmaf(h3, w2.w, bb.z))));
            float y3 = fmaf(h0, w3.x, fmaf(h1, w3.y, fmaf(h2, w3.z, fmaf(h3, w3.w, bb.w))));
            // sigmoid(y) = 1 / (1 + 2^(y'))
            h[k][0] = rcp_approx(1.0f + ex2_approx(y0));
            h[k][1] = rcp_approx(1.0f + ex2_approx(y1));
            h[k][2] = rcp_approx(1.0f + ex2_approx(y2));
            h[k][3] = rcp_approx(1.0f + ex2_approx(y3));
        }
    }

    // ---- head: Linear(4,1), coalesced stores ----
    float wo0 = sWout[0], wo1 = sWout[1], wo2 = sWout[2], wo3 = sWout[3];
    float bo = sbout;
    #pragma unroll
    for (int k = 0; k < RPT; k++) {
        float v = fmaf(h[k][0], wo0,
                  fmaf(h[k][1], wo1,
                  fmaf(h[k][2], wo2,
                  fmaf(h[k][3], wo3, bo))));
        out[tid + k * TOTAL_THREADS] = v;
    }
}

extern "C" void kernel_launch(void* const* d_in, const int* in_sizes, int n_in,
                              void* d_out, int out_size) {
    const float* x     = (const float*)d_in[0];
    const float* W_in  = (const float*)d_in[1];
    const float* b_in  = (const float*)d_in[2];
    const float* W_mid = (const float*)d_in[3];
    const float* b_mid = (const float*)d_in[4];
    const float* W_out = (const float*)d_in[5];
    const float* b_out = (const float*)d_in[6];
    float* out = (float*)d_out;

    mlp_kernel<<<NBLOCKS, TPB>>>(x, W_in, b_in, W_mid, b_mid, W_out, b_out, out);
}

// round 5
// speedup vs baseline: 1.9717x; 1.9717x over previous
#include <cuda_runtime.h>

// MLP_52759378264652: B=1048576, stem Linear(2,4)+ReLU,
// 98x [Linear(4,4)+Sigmoid], head Linear(4,1).
// Round 5: sigmoid via tanh half-angle, affine (0.5t+0.5) folded into the
// next layer's weights -> per row-layer exactly 16 FMA + 4 MUFU.TANH.

#define N_MID 98
#define BATCH 1048576
#define RPT 4
#define TPB 256
#define TOTAL_THREADS (BATCH / RPT)       // 262144
#define NBLOCKS (TOTAL_THREADS / TPB)     // 1024

__device__ __forceinline__ float tanh_approx(float x) {
    float r; asm("tanh.approx.f32 %0, %1;" : "=f"(r) : "f"(x)); return r;
}

__global__ __launch_bounds__(TPB) void mlp_kernel(
    const float* __restrict__ x,      // [B,2]
    const float* __restrict__ W_in,   // [4,2]
    const float* __restrict__ b_in,   // [4]
    const float* __restrict__ W_mid,  // [98,4,4]
    const float* __restrict__ b_mid,  // [98,4]
    const float* __restrict__ W_out,  // [1,4]
    const float* __restrict__ b_out,  // [1]
    float* __restrict__ out)          // [B,1]
{
    // Per-layer block of 20 floats: folded W''[4][4] then b''[4].
    // Stride 20 floats = 80 B (16B-aligned) so float4 loads land at +0/16/32/48/64.
    __shared__ float sW[N_MID * 20];
    __shared__ float sWin[8];
    __shared__ float sbin[4];
    __shared__ float sWout[4];
    __shared__ float sbout;

    // Folded weights:
    //   layer 0   : W'' = 0.5*W  (input is raw ReLU h, only tanh-half prescale)
    //   layer l>=1: W'' = 0.25*W (0.5 affine-fold * 0.5 tanh-half)
    for (int idx = threadIdx.x; idx < N_MID * 16; idx += TPB) {
        int l = idx >> 4, r = idx & 15;
        float s = (l == 0) ? 0.5f : 0.25f;
        sW[l * 20 + r] = W_mid[idx] * s;
    }
    // Folded biases: b'' = 0.5*b (+ 0.25*row-sum(W) for l>=1, from the
    // 0.5 constant part of h = 0.5*t + 0.5 feeding this layer).
    for (int idx = threadIdx.x; idx < N_MID * 4; idx += TPB) {
        int l = idx >> 2, j = idx & 3;
        float s = 0.5f * b_mid[idx];
        if (l > 0) {
            const float* wr = W_mid + l * 16 + j * 4;
            s += 0.25f * (wr[0] + wr[1] + wr[2] + wr[3]);
        }
        sW[l * 20 + 16 + j] = s;
    }
    if (threadIdx.x < 8) sWin[threadIdx.x] = W_in[threadIdx.x];
    if (threadIdx.x < 4) {
        sbin[threadIdx.x]  = b_in[threadIdx.x];
        sWout[threadIdx.x] = 0.5f * W_out[threadIdx.x];   // head: 0.5*t fold
    }
    if (threadIdx.x == 0)
        sbout = b_out[0] + 0.5f * (W_out[0] + W_out[1] + W_out[2] + W_out[3]);
    __syncthreads();

    const int tid = blockIdx.x * TPB + threadIdx.x;

    // t[k][j] holds the tanh-coded state: h = 0.5*t + 0.5 (after layer 0).
    float t[RPT][4];

    // ---- stem: Linear(2,4) + ReLU, coalesced float2 loads ----
    const float2* x2 = reinterpret_cast<const float2*>(x);
    #pragma unroll
    for (int k = 0; k < RPT; k++) {
        float2 xv = x2[tid + k * TOTAL_THREADS];
        #pragma unroll
        for (int j = 0; j < 4; j++) {
            float v = fmaf(xv.x, sWin[2 * j],
                      fmaf(xv.y, sWin[2 * j + 1], sbin[j]));
            t[k][j] = fmaxf(v, 0.0f);   // raw h for layer 0 (its W'' expects h)
        }
    }

    // ---- 98 x [Linear + tanh-coded sigmoid] ----
    #pragma unroll 1
    for (int l = 0; l < N_MID; l++) {
        const float4* wp = reinterpret_cast<const float4*>(sW + l * 20);
        float4 w0 = wp[0];
        float4 w1 = wp[1];
        float4 w2 = wp[2];
        float4 w3 = wp[3];
        float4 bb = wp[4];

        #pragma unroll
        for (int k = 0; k < RPT; k++) {
            float t0 = t[k][0], t1 = t[k][1], t2 = t[k][2], t3 = t[k][3];
            float y0 = fmaf(t0, w0.x, fmaf(t1, w0.y, fmaf(t2, w0.z, fmaf(t3, w0.w, bb.x))));
            float y1 = fmaf(t0, w1.x, fmaf(t1, w1.y, fmaf(t2, w1.z, fmaf(t3, w1.w, bb.y))));
            float y2 = fmaf(t0, w2.x, fmaf(t1, w2.y, fmaf(t2, w2.z, fmaf(t3, w2.w, bb.z))));
            float y3 = fmaf(t0, w3.x, fmaf(t1, w3.y, fmaf(t2, w3.z, fmaf(t3, w3.w, bb.w))));
            t[k][0] = tanh_approx(y0);
            t[k][1] = tanh_approx(y1);
            t[k][2] = tanh_approx(y2);
            t[k][3] = tanh_approx(y3);
        }
    }

    // ---- head: Linear(4,1) on tanh-coded state, coalesced stores ----
    float wo0 = sWout[0], wo1 = sWout[1], wo2 = sWout[2], wo3 = sWout[3];
    float bo = sbout;
    #pragma unroll
    for (int k = 0; k < RPT; k++) {
        float v = fmaf(t[k][0], wo0,
                  fmaf(t[k][1], wo1,
                  fmaf(t[k][2], wo2,
                  fmaf(t[k][3], wo3, bo))));
        out[tid + k * TOTAL_THREADS] = v;
    }
}

extern "C" void kernel_launch(void* const* d_in, const int* in_sizes, int n_in,
                              void* d_out, int out_size) {
    const float* x     = (const float*)d_in[0];
    const float* W_in  = (const float*)d_in[1];
    const float* b_in  = (const float*)d_in[2];
    const float* W_mid = (const float*)d_in[3];
    const float* b_mid = (const float*)d_in[4];
    const float* W_out = (const float*)d_in[5];
    const float* b_out = (const float*)d_in[6];
    float* out = (float*)d_out;

    mlp_kernel<<<NBLOCKS, TPB>>>(x, W_in, b_in, W_mid, b_mid, W_out, b_out, out);
}